// round 2
// baseline (speedup 1.0000x reference)
#include <cuda_runtime.h>

#define THREADS 256
#define C16 16
#define DIM 96
#define HW (DIM*DIM)
#define DHW (DIM*DIM*DIM)
#define FEATS 512
#define KTOT 1024
#define KSPLIT 2
#define KPB (KTOT/KSPLIT)          // 512 k per block
#define SMEM_FLOATS 12288          // 48 KB dynamic smem
#define CAPVOX (SMEM_FLOATS/C16)   // 768 voxels max brick

extern __shared__ float smem[];

__global__ void __launch_bounds__(THREADS)
obelisk_kernel(const float* __restrict__ vol,
               const float* __restrict__ xyz,
               const float* __restrict__ Amat,
               const float* __restrict__ W6,
               float* __restrict__ out)
{
    const int tid = threadIdx.x;
    const int blk = blockIdx.x;
    const int pt  = blk >> 1;     // 0..B*FEATS-1
    const int kh  = blk & 1;
    const int b   = pt >> 9;      // / FEATS
    const int f   = pt & (FEATS - 1);
    const int k0  = kh * KPB;

    __shared__ float sP[12];   // bx,by,bz, ax0..2, ay0..2, az0..2
    __shared__ int   sBox[7];  // xlo,ylo,zlo,nx,ny,nz,mode

    if (tid == 0) {
        float x0 = xyz[pt*3+0], x1 = xyz[pt*3+1], x2 = xyz[pt*3+2];
        // grid_sample x-axis (W) uses grid[...,0] = xs[0] + A_row2 . w
        // y-axis (H) uses grid[...,1] = xs[1] + A_row1 . w
        // z-axis (D) uses grid[...,2] = xs[2] + A_row0 . w
        sP[0] = (x0 + 1.f) * 48.f - 0.5f;
        sP[1] = (x1 + 1.f) * 48.f - 0.5f;
        sP[2] = (x2 + 1.f) * 48.f - 0.5f;
        const float* Ar = Amat + pt * 9;
        sP[3] = 48.f*Ar[6]; sP[4]  = 48.f*Ar[7]; sP[5]  = 48.f*Ar[8];  // x row
        sP[6] = 48.f*Ar[3]; sP[7]  = 48.f*Ar[4]; sP[8]  = 48.f*Ar[5];  // y row
        sP[9] = 48.f*Ar[0]; sP[10] = 48.f*Ar[1]; sP[11] = 48.f*Ar[2];  // z row
    }
    __syncthreads();

    const float bx = sP[0], by = sP[1], bz = sP[2];
    const float ax0 = sP[3], ax1 = sP[4],  ax2 = sP[5];
    const float ay0 = sP[6], ay1 = sP[7],  ay2 = sP[8];
    const float az0 = sP[9], az1 = sP[10], az2 = sP[11];

    // ---------------- Pass 1: bounding box of all sample coords ----------------
    float mnx = 1e30f, mxx = -1e30f;
    float mny = 1e30f, mxy = -1e30f;
    float mnz = 1e30f, mxz = -1e30f;
    for (int k = k0 + tid; k < k0 + KPB; k += THREADS) {
        #pragma unroll
        for (int s = 0; s < 2; s++) {
            const float* wp = W6 + s*3*KTOT + k;
            float w0 = __ldg(wp);
            float w1 = __ldg(wp + KTOT);
            float w2 = __ldg(wp + 2*KTOT);
            float px = fmaf(ax0, w0, fmaf(ax1, w1, fmaf(ax2, w2, bx)));
            float py = fmaf(ay0, w0, fmaf(ay1, w1, fmaf(ay2, w2, by)));
            float pz = fmaf(az0, w0, fmaf(az1, w1, fmaf(az2, w2, bz)));
            mnx = fminf(mnx, px); mxx = fmaxf(mxx, px);
            mny = fminf(mny, py); mxy = fmaxf(mxy, py);
            mnz = fminf(mnz, pz); mxz = fmaxf(mxz, pz);
        }
    }
    float* red = smem;
    red[tid]             = mnx; red[THREADS   + tid] = mxx;
    red[2*THREADS + tid] = mny; red[3*THREADS + tid] = mxy;
    red[4*THREADS + tid] = mnz; red[5*THREADS + tid] = mxz;
    __syncthreads();
    for (int s2 = THREADS/2; s2 > 0; s2 >>= 1) {
        if (tid < s2) {
            red[tid]             = fminf(red[tid],             red[tid + s2]);
            red[THREADS   + tid] = fmaxf(red[THREADS   + tid], red[THREADS   + tid + s2]);
            red[2*THREADS + tid] = fminf(red[2*THREADS + tid], red[2*THREADS + tid + s2]);
            red[3*THREADS + tid] = fmaxf(red[3*THREADS + tid], red[3*THREADS + tid + s2]);
            red[4*THREADS + tid] = fminf(red[4*THREADS + tid], red[4*THREADS + tid + s2]);
            red[5*THREADS + tid] = fmaxf(red[5*THREADS + tid], red[5*THREADS + tid + s2]);
        }
        __syncthreads();
    }
    if (tid == 0) {
        int xlo = max(0, (int)floorf(red[0]));
        int xhi = min(DIM - 1, (int)floorf(red[THREADS]) + 1);
        int ylo = max(0, (int)floorf(red[2*THREADS]));
        int yhi = min(DIM - 1, (int)floorf(red[3*THREADS]) + 1);
        int zlo = max(0, (int)floorf(red[4*THREADS]));
        int zhi = min(DIM - 1, (int)floorf(red[5*THREADS]) + 1);
        int nx = xhi - xlo + 1, ny = yhi - ylo + 1, nz = zhi - zlo + 1;
        int mode;
        if (nx <= 0 || ny <= 0 || nz <= 0) mode = 2;                   // fully outside
        else if ((long)nx * ny * nz <= CAPVOX) mode = 0;               // smem brick
        else mode = 1;                                                 // global fallback
        sBox[0] = xlo; sBox[1] = ylo; sBox[2] = zlo;
        sBox[3] = nx;  sBox[4] = ny;  sBox[5] = nz;
        sBox[6] = mode;
    }
    __syncthreads();

    const int xlo = sBox[0], ylo = sBox[1], zlo = sBox[2];
    const int nx = sBox[3], ny = sBox[4], nz = sBox[5];
    const int mode = sBox[6];

    const size_t out_base0 = (((size_t)b * C16) * FEATS + f) * KTOT;

    if (mode == 2) {
        for (int k = k0 + tid; k < k0 + KPB; k += THREADS) {
            #pragma unroll
            for (int c = 0; c < C16; c++)
                out[out_base0 + (size_t)c * (FEATS*KTOT) + k] = 0.f;
        }
        return;
    }

    const float* volb = vol + (size_t)b * C16 * DHW;
    const int nyx = ny * nx;
    const int PS  = nz * nyx;  // per-channel brick plane size

    // ---------------- Brick load ----------------
    if (mode == 0) {
        const int E = C16 * PS;
        for (int m = tid; m < E; m += THREADS) {
            int x  = m % nx;
            int t  = m / nx;
            int y  = t % ny;
            int t2 = t / ny;
            int z  = t2 % nz;
            int c  = t2 / nz;
            smem[m] = __ldg(volb + (size_t)c * DHW
                            + (size_t)(zlo + z) * HW + (ylo + y) * DIM + (xlo + x));
        }
    }
    __syncthreads();

    // ---------------- Main sampling loop ----------------
    if (mode == 0) {
        for (int k = k0 + tid; k < k0 + KPB; k += THREADS) {
            float acc[C16];
            #pragma unroll
            for (int c = 0; c < C16; c++) acc[c] = 0.f;

            #pragma unroll
            for (int s = 0; s < 2; s++) {
                const float* wp = W6 + s*3*KTOT + k;
                float w0 = __ldg(wp);
                float w1 = __ldg(wp + KTOT);
                float w2 = __ldg(wp + 2*KTOT);
                float px = fmaf(ax0, w0, fmaf(ax1, w1, fmaf(ax2, w2, bx)));
                float py = fmaf(ay0, w0, fmaf(ay1, w1, fmaf(ay2, w2, by)));
                float pz = fmaf(az0, w0, fmaf(az1, w1, fmaf(az2, w2, bz)));
                float fx = floorf(px), fy = floorf(py), fz = floorf(pz);
                float tx = px - fx, ty = py - fy, tz = pz - fz;
                int jx0 = (int)fx - xlo, jy0 = (int)fy - ylo, jz0 = (int)fz - zlo;
                int jx1 = jx0 + 1, jy1 = jy0 + 1, jz1 = jz0 + 1;
                float wx0 = 1.f - tx, wx1 = tx;
                float wy0 = 1.f - ty, wy1 = ty;
                float wz0 = 1.f - tz, wz1 = tz;
                // zero-weight + clamp for out-of-brick (== out-of-volume) corners
                if ((unsigned)jx0 >= (unsigned)nx) { wx0 = 0.f; jx0 = 0; }
                if ((unsigned)jx1 >= (unsigned)nx) { wx1 = 0.f; jx1 = 0; }
                if ((unsigned)jy0 >= (unsigned)ny) { wy0 = 0.f; jy0 = 0; }
                if ((unsigned)jy1 >= (unsigned)ny) { wy1 = 0.f; jy1 = 0; }
                if ((unsigned)jz0 >= (unsigned)nz) { wz0 = 0.f; jz0 = 0; }
                if ((unsigned)jz1 >= (unsigned)nz) { wz1 = 0.f; jz1 = 0; }
                float sg = s ? -1.f : 1.f;
                float wzy00 = wz0*wy0*sg, wzy01 = wz0*wy1*sg;
                float wzy10 = wz1*wy0*sg, wzy11 = wz1*wy1*sg;
                int r00 = jz0*nyx + jy0*nx, r01 = jz0*nyx + jy1*nx;
                int r10 = jz1*nyx + jy0*nx, r11 = jz1*nyx + jy1*nx;
                int offs[8] = { r00+jx0, r00+jx1, r01+jx0, r01+jx1,
                                r10+jx0, r10+jx1, r11+jx0, r11+jx1 };
                float wgt[8] = { wzy00*wx0, wzy00*wx1, wzy01*wx0, wzy01*wx1,
                                 wzy10*wx0, wzy10*wx1, wzy11*wx0, wzy11*wx1 };
                #pragma unroll
                for (int c = 0; c < C16; c++) {
                    const float* pc = smem + c * PS;
                    float a = acc[c];
                    #pragma unroll
                    for (int j = 0; j < 8; j++) a = fmaf(wgt[j], pc[offs[j]], a);
                    acc[c] = a;
                }
            }
            #pragma unroll
            for (int c = 0; c < C16; c++)
                out[out_base0 + (size_t)c * (FEATS*KTOT) + k] = acc[c];
        }
    } else {
        // mode 1: rare oversized bbox -> direct global gathers
        for (int k = k0 + tid; k < k0 + KPB; k += THREADS) {
            float acc[C16];
            #pragma unroll
            for (int c = 0; c < C16; c++) acc[c] = 0.f;

            #pragma unroll
            for (int s = 0; s < 2; s++) {
                const float* wp = W6 + s*3*KTOT + k;
                float w0 = __ldg(wp);
                float w1 = __ldg(wp + KTOT);
                float w2 = __ldg(wp + 2*KTOT);
                float px = fmaf(ax0, w0, fmaf(ax1, w1, fmaf(ax2, w2, bx)));
                float py = fmaf(ay0, w0, fmaf(ay1, w1, fmaf(ay2, w2, by)));
                float pz = fmaf(az0, w0, fmaf(az1, w1, fmaf(az2, w2, bz)));
                float fx = floorf(px), fy = floorf(py), fz = floorf(pz);
                float tx = px - fx, ty = py - fy, tz = pz - fz;
                int jx0 = (int)fx, jy0 = (int)fy, jz0 = (int)fz;
                int jx1 = jx0 + 1, jy1 = jy0 + 1, jz1 = jz0 + 1;
                float wx0 = 1.f - tx, wx1 = tx;
                float wy0 = 1.f - ty, wy1 = ty;
                float wz0 = 1.f - tz, wz1 = tz;
                if ((unsigned)jx0 >= (unsigned)DIM) { wx0 = 0.f; jx0 = 0; }
                if ((unsigned)jx1 >= (unsigned)DIM) { wx1 = 0.f; jx1 = 0; }
                if ((unsigned)jy0 >= (unsigned)DIM) { wy0 = 0.f; jy0 = 0; }
                if ((unsigned)jy1 >= (unsigned)DIM) { wy1 = 0.f; jy1 = 0; }
                if ((unsigned)jz0 >= (unsigned)DIM) { wz0 = 0.f; jz0 = 0; }
                if ((unsigned)jz1 >= (unsigned)DIM) { wz1 = 0.f; jz1 = 0; }
                float sg = s ? -1.f : 1.f;
                float wzy00 = wz0*wy0*sg, wzy01 = wz0*wy1*sg;
                float wzy10 = wz1*wy0*sg, wzy11 = wz1*wy1*sg;
                int r00 = jz0*HW + jy0*DIM, r01 = jz0*HW + jy1*DIM;
                int r10 = jz1*HW + jy0*DIM, r11 = jz1*HW + jy1*DIM;
                int offs[8] = { r00+jx0, r00+jx1, r01+jx0, r01+jx1,
                                r10+jx0, r10+jx1, r11+jx0, r11+jx1 };
                float wgt[8] = { wzy00*wx0, wzy00*wx1, wzy01*wx0, wzy01*wx1,
                                 wzy10*wx0, wzy10*wx1, wzy11*wx0, wzy11*wx1 };
                #pragma unroll
                for (int c = 0; c < C16; c++) {
                    const float* pc = volb + (size_t)c * DHW;
                    float a = acc[c];
                    #pragma unroll
                    for (int j = 0; j < 8; j++) a = fmaf(wgt[j], __ldg(pc + offs[j]), a);
                    acc[c] = a;
                }
            }
            #pragma unroll
            for (int c = 0; c < C16; c++)
                out[out_base0 + (size_t)c * (FEATS*KTOT) + k] = acc[c];
        }
    }
}

extern "C" void kernel_launch(void* const* d_in, const int* in_sizes, int n_in,
                              void* d_out, int out_size)
{
    const float* vol  = (const float*)d_in[0];  // [2,16,96,96,96]
    const float* xyz  = (const float*)d_in[1];  // [2,512,3]
    const float* Amat = (const float*)d_in[2];  // [1024,3,3]
    const float* W6   = (const float*)d_in[3];  // [6,1024]
    float* out = (float*)d_out;                 // [2, 16*512, 1024]

    // Opt in to >48KB-combined shared memory (dynamic 48KB + small static).
    // Attribute set, not a stream op — legal during graph capture.
    cudaFuncSetAttribute(obelisk_kernel,
                         cudaFuncAttributeMaxDynamicSharedMemorySize,
                         SMEM_FLOATS * (int)sizeof(float));

    const int nblocks = KSPLIT * 2 * FEATS;     // 2048
    obelisk_kernel<<<nblocks, THREADS, SMEM_FLOATS * sizeof(float)>>>(
        vol, xyz, Amat, W6, out);
}